// round 2
// baseline (speedup 1.0000x reference)
#include <cuda_runtime.h>
#include <math.h>

#define BB 2
#define CC 64
#define ZZ 8
#define HH 32
#define WW 32
#define GG 4
#define DD 16
#define NN 1024
#define ZHW (ZZ*HH*WW)   /* 8192 */

// ---------------- scratch (device globals; no allocation allowed) ----------
__device__ float g_xn [BB*CC*ZHW];          // BN output              4 MB
__device__ float g_qkv[BB*3*CC*ZHW];        // qkv conv output       12 MB
__device__ float g_q  [BB*GG*ZZ*NN*DD];     // normalized q, [bgz][i][d]
__device__ float g_kt [BB*GG*ZZ*NN*DD];     // normalized k, [bgz][j][d]
__device__ float g_v  [BB*GG*ZZ*NN*DD];     // normalized v, [bgz][j][d]
__device__ float g_ao [BB*CC*ZHW];          // attention out, NCDHW layout
__device__ float g_mean[CC], g_rstd[CC];
__device__ float g_E[GG*63];                // exp(-fac*(delta/32)^2), delta=-31..31
__device__ float g_S[GG*32];                // 1D row sums

// ---------------- BN statistics (per channel over B*Z*H*W = 16384) ---------
__global__ void bn_stats_kernel(const float* __restrict__ x) {
    int c = blockIdx.x;
    const float* p0 = x + c*ZHW;
    float s = 0.f, sq = 0.f;
    for (int i = threadIdx.x; i < ZHW; i += 256) {
        float a = p0[i];
        float b = p0[CC*ZHW + i];
        s += a + b; sq += a*a + b*b;
    }
    __shared__ float rs[256], rq[256];
    rs[threadIdx.x] = s; rq[threadIdx.x] = sq; __syncthreads();
    for (int o = 128; o > 0; o >>= 1) {
        if (threadIdx.x < o) { rs[threadIdx.x] += rs[threadIdx.x+o]; rq[threadIdx.x] += rq[threadIdx.x+o]; }
        __syncthreads();
    }
    if (threadIdx.x == 0) {
        float inv_n = 1.f / (float)(BB*ZHW);
        float m = rs[0] * inv_n;
        float v = rq[0] * inv_n - m*m;
        g_mean[c] = m;
        g_rstd[c] = rsqrtf(v + 1e-5f);
    }
}

// ---------------- apply BN -------------------------------------------------
__global__ void bn_apply_kernel(const float* __restrict__ x,
                                const float* __restrict__ gamma,
                                const float* __restrict__ beta) {
    int i = blockIdx.x*256 + threadIdx.x;
    int c = (i >> 13) & (CC-1);      // i / 8192 % 64
    g_xn[i] = (x[i] - g_mean[c]) * g_rstd[c] * gamma[c] + beta[c];
}

// ---------------- separable distance-decay tables --------------------------
__global__ void dis_tables_kernel(const float* __restrict__ headsita) {
    __shared__ float fac[GG];
    int t = threadIdx.x;
    if (t < GG) {
        float sig = 1.f / (1.f + expf(-headsita[t]));
        float den = sig * (0.4f - 0.003f) + 0.003f;
        fac[t] = 1.f / (2.f * den * den);
    }
    __syncthreads();
    if (t < GG*63) {
        int g = t / 63, idx = t - g*63;
        float d = (float)(idx - 31) / 32.f;
        g_E[t] = expf(-fac[g] * d * d);
    }
    if (t < GG*32) {
        int g = t >> 5, a = t & 31;
        float s = 0.f;
        for (int b = 0; b < 32; b++) {
            float d = (float)(a - b) / 32.f;
            s += expf(-fac[g] * d * d);
        }
        g_S[t] = s;
    }
}

// ---------------- direct 3x3x3 conv, smem-tiled ----------------------------
// grid.x = b*8+z (16), grid.y = cout/8 groups; 256 threads, 4 positions each.
template<int CIN, int COPB>
__global__ void conv3d_kernel(const float* __restrict__ in,
                              const float* __restrict__ wgt,
                              float* __restrict__ out) {
    int b = blockIdx.x >> 3, z = blockIdx.x & 7;
    int cobase = blockIdx.y * COPB;
    int cout_total = gridDim.y * COPB;
    __shared__ float xs[3*34*34];
    __shared__ float ws[COPB*27];
    float acc[4][COPB];
    #pragma unroll
    for (int p = 0; p < 4; p++)
        #pragma unroll
        for (int co = 0; co < COPB; co++) acc[p][co] = 0.f;
    int tid = threadIdx.x;

    for (int ci = 0; ci < CIN; ci++) {
        __syncthreads();
        for (int idx = tid; idx < 3*34*34; idx += 256) {
            int kz = idx / 1156, rem = idx - kz*1156;
            int yy = rem / 34, xx = rem - yy*34;
            int zz = z + kz - 1, y = yy - 1, x = xx - 1;
            float v = 0.f;
            if ((unsigned)zz < 8u && (unsigned)y < 32u && (unsigned)x < 32u)
                v = in[((b*CIN + ci)*8 + zz)*1024 + y*32 + x];
            xs[idx] = v;
        }
        for (int idx = tid; idx < COPB*27; idx += 256) {
            int co = idx / 27, k = idx - co*27;
            ws[idx] = wgt[((cobase + co)*CIN + ci)*27 + k];
        }
        __syncthreads();
        #pragma unroll
        for (int p = 0; p < 4; p++) {
            int pos = tid + p*256;
            int y = pos >> 5, x = pos & 31;
            float r[27];
            #pragma unroll
            for (int kz = 0; kz < 3; kz++)
                #pragma unroll
                for (int ky = 0; ky < 3; ky++)
                    #pragma unroll
                    for (int kx = 0; kx < 3; kx++)
                        r[kz*9 + ky*3 + kx] = xs[kz*1156 + (y+ky)*34 + (x+kx)];
            #pragma unroll
            for (int co = 0; co < COPB; co++) {
                float a = acc[p][co];
                #pragma unroll
                for (int k = 0; k < 27; k++) a = fmaf(r[k], ws[co*27 + k], a);
                acc[p][co] = a;
            }
        }
    }
    #pragma unroll
    for (int p = 0; p < 4; p++)
        #pragma unroll
        for (int co = 0; co < COPB; co++)
            out[((b*cout_total + cobase + co)*8 + z)*1024 + tid + p*256] = acc[p][co];
    (void)cout_total;
}

// ---------------- q/v normalize over d (16), transpose to [i][d] -----------
__global__ void qv_norm_kernel() {
    int bgz = blockIdx.x;                  // 64
    int b = bgz >> 5, gz = bgz & 31;
    int g = gz >> 3, z = gz & 7;
    for (int ii = 0; ii < 4; ii++) {
        int i = threadIdx.x + ii*256;
        float qv[16], vv[16];
        float sq = 0.f, sv = 0.f;
        #pragma unroll
        for (int dd = 0; dd < 16; dd++) {
            float a = g_qkv[((b*192       + g*16 + dd)*8 + z)*1024 + i];
            float c = g_qkv[((b*192 + 128 + g*16 + dd)*8 + z)*1024 + i];
            qv[dd] = a; vv[dd] = c;
            sq += a*a; sv += c*c;
        }
        float rq = 1.f / fmaxf(sqrtf(sq), 1e-12f);
        float rv = 1.f / fmaxf(sqrtf(sv), 1e-12f);
        int base = (bgz*1024 + i)*16;
        #pragma unroll
        for (int dd = 0; dd < 16; dd++) {
            g_q[base + dd] = qv[dd]*rq;
            g_v[base + dd] = vv[dd]*rv;
        }
    }
}

// ---------------- k normalize over n (1024), transpose to [j][d] -----------
__global__ void k_norm_kernel() {
    int id = blockIdx.x;                   // 1024 = bgz*16 + dd
    int bgz = id >> 4, dd = id & 15;
    int b = bgz >> 5, g = (bgz >> 3) & 3, z = bgz & 7;
    const float* row = g_qkv + ((b*192 + 64 + g*16 + dd)*8 + z)*1024;
    float s = 0.f;
    for (int i = threadIdx.x; i < 1024; i += 256) { float a = row[i]; s += a*a; }
    __shared__ float rs[256];
    rs[threadIdx.x] = s; __syncthreads();
    for (int o = 128; o > 0; o >>= 1) {
        if (threadIdx.x < o) rs[threadIdx.x] += rs[threadIdx.x+o];
        __syncthreads();
    }
    float r = 1.f / fmaxf(sqrtf(rs[0]), 1e-12f);
    for (int i = threadIdx.x; i < 1024; i += 256)
        g_kt[(bgz*1024 + i)*16 + dd] = row[i] * r;
}

// ---------------- fused (dis o q k^T) v attention --------------------------
// 256 blocks: bgz(64) x 4 i-tiles of 256 rows; 1 thread = 1 query row.
__global__ void attn_kernel() {
    int bgz = blockIdx.x >> 2, it = blockIdx.x & 3;
    int b = bgz >> 5, g = (bgz >> 3) & 3, z = bgz & 7;
    int i = it*256 + threadIdx.x;
    int hi = i >> 5, wi = i & 31;

    __shared__ float kts[128*16];
    __shared__ float vs [128*16];
    __shared__ float Es[64];
    __shared__ float Ss[32];
    if (threadIdx.x < 63) Es[threadIdx.x] = g_E[g*63 + threadIdx.x];
    if (threadIdx.x < 32) Ss[threadIdx.x] = g_S[g*32 + threadIdx.x];
    __syncthreads();

    float inv = 1.f / (Ss[hi] * Ss[wi]);   // fold 1/rowsum into q row
    float q[16], acc[16];
    const float* qp = g_q + (bgz*1024 + i)*16;
    #pragma unroll
    for (int dd = 0; dd < 16; dd++) { q[dd] = qp[dd] * inv; acc[dd] = 0.f; }

    const float4* k4 = (const float4*)(g_kt + bgz*1024*16);
    const float4* v4 = (const float4*)(g_v  + bgz*1024*16);
    float4* ks4 = (float4*)kts;
    float4* vs4 = (float4*)vs;

    for (int j0 = 0; j0 < 1024; j0 += 128) {
        __syncthreads();
        int off = j0*4;  // float4 offset
        for (int idx = threadIdx.x; idx < 512; idx += 256) {
            ks4[idx] = k4[off + idx];
            vs4[idx] = v4[off + idx];
        }
        __syncthreads();
        #pragma unroll 4
        for (int jj = 0; jj < 128; jj++) {
            const float* kr = &kts[jj*16];
            float s0 = 0.f, s1 = 0.f, s2 = 0.f, s3 = 0.f;
            #pragma unroll
            for (int dd = 0; dd < 4; dd++) {
                s0 = fmaf(q[dd],    kr[dd],    s0);
                s1 = fmaf(q[dd+4],  kr[dd+4],  s1);
                s2 = fmaf(q[dd+8],  kr[dd+8],  s2);
                s3 = fmaf(q[dd+12], kr[dd+12], s3);
            }
            float s = (s0 + s1) + (s2 + s3);
            int jg = j0 + jj, hj = jg >> 5, wj = jg & 31;
            s *= Es[hi - hj + 31] * Es[wi - wj + 31];
            const float* vr = &vs[jj*16];
            #pragma unroll
            for (int dd = 0; dd < 16; dd++) acc[dd] = fmaf(s, vr[dd], acc[dd]);
        }
    }
    #pragma unroll
    for (int dd = 0; dd < 16; dd++)
        g_ao[((b*64 + g*16 + dd)*8 + z)*1024 + i] = acc[dd];
}

// ---------------- launch ---------------------------------------------------
extern "C" void kernel_launch(void* const* d_in, const int* in_sizes, int n_in,
                              void* d_out, int out_size) {
    const float* x        = (const float*)d_in[0];
    const float* bn_gamma = (const float*)d_in[1];
    const float* bn_beta  = (const float*)d_in[2];
    const float* w_qkv    = (const float*)d_in[3];
    const float* headsita = (const float*)d_in[4];
    const float* w_conv   = (const float*)d_in[5];
    float* out = (float*)d_out;

    float *p_xn, *p_qkv, *p_ao;
    cudaGetSymbolAddress((void**)&p_xn,  g_xn);
    cudaGetSymbolAddress((void**)&p_qkv, g_qkv);
    cudaGetSymbolAddress((void**)&p_ao,  g_ao);

    bn_stats_kernel<<<CC, 256>>>(x);
    dis_tables_kernel<<<1, 256>>>(headsita);
    bn_apply_kernel<<<(BB*CC*ZHW)/256, 256>>>(x, bn_gamma, bn_beta);
    conv3d_kernel<64, 8><<<dim3(16, 24), 256>>>(p_xn, w_qkv, p_qkv);   // 192 out ch
    qv_norm_kernel<<<64, 256>>>();
    k_norm_kernel<<<1024, 256>>>();
    attn_kernel<<<256, 256>>>();
    conv3d_kernel<64, 8><<<dim3(16, 8), 256>>>(p_ao, w_conv, out);     // 64 out ch
    (void)in_sizes; (void)n_in; (void)out_size;
}